// round 3
// baseline (speedup 1.0000x reference)
#include <cuda_runtime.h>

// Problem constants
#define BB   8
#define NN   8192
#define SS   2048
#define C1K  128
#define C2K  256
#define INCH 384            // C1 + C2
#define H1   256
#define H2   128
#define MM   (BB * NN)      // 65536 total points

typedef unsigned long long u64;

// ---------------- scratch (static device globals; no allocation) ----------------
__device__ float g_X  [MM * (size_t)INCH];   // concat(p1, interp)  [M, 384]
__device__ float g_Y1 [MM * (size_t)H1];     // pre-BN layer1 out   [M, 256]
__device__ float g_Y2 [MM * (size_t)H2];     // pre-BN layer2 out   [M, 128]
__device__ float g_P2T[BB * (size_t)SS * C2K]; // points2 transposed [B, S, C2]
__device__ int   g_idx[MM * 3];
__device__ float g_wt [MM * 3];
__device__ float g_sum1[H1], g_sq1[H1], g_sum2[H2], g_sq2[H2];
__device__ float g_sc1 [H1], g_sh1[H1], g_sc2 [H2], g_sh2[H2];

__device__ __forceinline__ u64 ffma2(u64 a, u64 b, u64 c) {
    u64 d;
    asm("fma.rn.f32x2 %0, %1, %2, %3;" : "=l"(d) : "l"(a), "l"(b), "l"(c));
    return d;
}

// ---------------- zero the per-channel accumulators ----------------
__global__ void zero_stats_kernel() {
    int t = threadIdx.x;
    g_sum1[t] = 0.f; g_sq1[t] = 0.f;
    if (t < H2) { g_sum2[t] = 0.f; g_sq2[t] = 0.f; }
}

// ---------------- tiled transpose: src [B][C][L] -> dst [B][L][ldDst] ----------------
__global__ void transpose_kernel(const float* __restrict__ src, float* __restrict__ dst,
                                 int C, int L, int ldDst)
{
    __shared__ float tile[32][33];
    int b  = blockIdx.z;
    int l0 = blockIdx.x * 32, c0 = blockIdx.y * 32;
    const float* s = src + (size_t)b * C * L;
    float*       d = dst + (size_t)b * L * ldDst;
    int tx = threadIdx.x, ty = threadIdx.y;
#pragma unroll
    for (int i = 0; i < 4; i++)
        tile[ty + i * 8][tx] = s[(size_t)(c0 + ty + i * 8) * L + l0 + tx];
    __syncthreads();
#pragma unroll
    for (int i = 0; i < 4; i++)
        d[(size_t)(l0 + ty + i * 8) * ldDst + c0 + tx] = tile[tx][ty + i * 8];
}

// ---------------- 3-NN over S=2048 candidates (smem resident, 2 points/thread) ----------------
__global__ void knn_kernel(const float* __restrict__ xyz1, const float* __restrict__ xyz2)
{
    __shared__ float4 sq[SS];               // {x, y, z, |q|^2}  32KB
    int b = blockIdx.y;
    const float* x2 = xyz2 + (size_t)b * 3 * SS;
    for (int s = threadIdx.x; s < SS; s += blockDim.x) {
        float qx = x2[s], qy = x2[SS + s], qz = x2[2 * SS + s];
        sq[s] = make_float4(qx, qy, qz, qx * qx + qy * qy + qz * qz);
    }
    __syncthreads();

    int nA = blockIdx.x * 512 + threadIdx.x;
    int nB = nA + 256;
    const float* x1 = xyz1 + (size_t)b * 3 * NN;
    float pxA = x1[nA], pyA = x1[NN + nA], pzA = x1[2 * NN + nA];
    float pxB = x1[nB], pyB = x1[NN + nB], pzB = x1[2 * NN + nB];
    float mxA = -2.f * pxA, myA = -2.f * pyA, mzA = -2.f * pzA;
    float mxB = -2.f * pxB, myB = -2.f * pyB, mzB = -2.f * pzB;
    float p2A = pxA * pxA + pyA * pyA + pzA * pzA;
    float p2B = pxB * pxB + pyB * pyB + pzB * pzB;

    float a0 = 1e30f, a1 = 1e30f, a2 = 1e30f;
    float c0 = 1e30f, c1 = 1e30f, c2 = 1e30f;
    int   ia0 = 0, ia1 = 0, ia2 = 0, ib0 = 0, ib1 = 0, ib2 = 0;
#pragma unroll 4
    for (int s = 0; s < SS; s++) {
        float4 q = sq[s];
        float tA = fmaf(mxA, q.x, fmaf(myA, q.y, fmaf(mzA, q.z, q.w)));
        float tB = fmaf(mxB, q.x, fmaf(myB, q.y, fmaf(mzB, q.z, q.w)));
        if (tA < a2) {
            if (tA < a1) {
                a2 = a1; ia2 = ia1;
                if (tA < a0) { a1 = a0; ia1 = ia0; a0 = tA; ia0 = s; }
                else         { a1 = tA; ia1 = s; }
            } else { a2 = tA; ia2 = s; }
        }
        if (tB < c2) {
            if (tB < c1) {
                c2 = c1; ib2 = ib1;
                if (tB < c0) { c1 = c0; ib1 = ib0; c0 = tB; ib0 = s; }
                else         { c1 = tB; ib1 = s; }
            } else { c2 = tB; ib2 = s; }
        }
    }
    {
        float e0 = a0 + p2A, e1 = a1 + p2A, e2 = a2 + p2A;
        float r0 = 1.f / (e0 + 1e-8f), r1 = 1.f / (e1 + 1e-8f), r2 = 1.f / (e2 + 1e-8f);
        float rs = 1.f / (r0 + r1 + r2);
        size_t base = ((size_t)b * NN + nA) * 3;
        g_idx[base] = ia0; g_idx[base + 1] = ia1; g_idx[base + 2] = ia2;
        g_wt [base] = r0 * rs; g_wt[base + 1] = r1 * rs; g_wt[base + 2] = r2 * rs;
    }
    {
        float e0 = c0 + p2B, e1 = c1 + p2B, e2 = c2 + p2B;
        float r0 = 1.f / (e0 + 1e-8f), r1 = 1.f / (e1 + 1e-8f), r2 = 1.f / (e2 + 1e-8f);
        float rs = 1.f / (r0 + r1 + r2);
        size_t base = ((size_t)b * NN + nB) * 3;
        g_idx[base] = ib0; g_idx[base + 1] = ib1; g_idx[base + 2] = ib2;
        g_wt [base] = r0 * rs; g_wt[base + 1] = r1 * rs; g_wt[base + 2] = r2 * rs;
    }
}

// ---------------- weighted gather of 3 rows from P2T -> X[:,128:384] ----------------
__global__ void interp_kernel()
{
    int b  = blockIdx.y;
    int c  = threadIdx.x;                  // channel 0..255
    int n0 = blockIdx.x * 32;
    const float* p2t = g_P2T + (size_t)b * SS * C2K;
#pragma unroll 4
    for (int r = 0; r < 32; r++) {
        size_t m = (size_t)b * NN + n0 + r;
        int   j0 = g_idx[m * 3], j1 = g_idx[m * 3 + 1], j2 = g_idx[m * 3 + 2];
        float w0 = g_wt[m * 3], w1 = g_wt[m * 3 + 1], w2 = g_wt[m * 3 + 2];
        float v = w0 * p2t[(size_t)j0 * C2K + c]
                + w1 * p2t[(size_t)j1 * C2K + c]
                + w2 * p2t[(size_t)j2 * C2K + c];
        g_X[m * INCH + C1K + c] = v;
    }
}

// ---------------- fp32x2 tiled GEMM: Y[m][n] = sum_k f(A[m][k]) * W[n][k] + bias[n] ----------------
// BM=128, BN=128, BK=16, 256 threads, 8x8 per thread via packed fma.rn.f32x2.
// A tile is stored DUPLICATED in smem ({a,a} pairs) so both FFMA2 operands are
// natural 64-bit smem loads. Column stats (sum/sumsq) fused into the epilogue.
template <int K, bool BNRELU>
__global__ __launch_bounds__(256) void gemm_kernel(
    const float* __restrict__ A, const float* __restrict__ W, const float* __restrict__ bias,
    const float* __restrict__ sc, const float* __restrict__ sh,
    float* __restrict__ Y, int ldc,
    float* __restrict__ osum, float* __restrict__ osq)
{
    __shared__ float Asd[16][264];   // duplicated A: [k][2*m] (pairs {a,a})
    __shared__ float Bs [16][132];   // [k][n]
    int tid = threadIdx.x;
    int m0 = blockIdx.x * 128;
    int n0 = blockIdx.y * 128;
    int lr = tid >> 2;            // 0..63 (row within half-tile)
    int lc = (tid & 3) * 4;       // k offset: 0,4,8,12
    int ty = tid >> 4, tx = tid & 15;

    u64 acc2[8][4];               // [i = m-row 0..7][j = n-pair 0..3]
#pragma unroll
    for (int i = 0; i < 8; i++)
#pragma unroll
        for (int j = 0; j < 4; j++) acc2[i][j] = 0ull;

    for (int k0 = 0; k0 < K; k0 += 16) {
#pragma unroll
        for (int h = 0; h < 2; h++) {
            int row = lr + h * 64;
            float4 a = *(const float4*)&A[(size_t)(m0 + row) * K + k0 + lc];
            if (BNRELU) {
                float4 s4 = *(const float4*)&sc[k0 + lc];
                float4 t4 = *(const float4*)&sh[k0 + lc];
                a.x = fmaxf(fmaf(a.x, s4.x, t4.x), 0.f);
                a.y = fmaxf(fmaf(a.y, s4.y, t4.y), 0.f);
                a.z = fmaxf(fmaf(a.z, s4.z, t4.z), 0.f);
                a.w = fmaxf(fmaf(a.w, s4.w, t4.w), 0.f);
            }
            *(float2*)&Asd[lc + 0][2 * row] = make_float2(a.x, a.x);
            *(float2*)&Asd[lc + 1][2 * row] = make_float2(a.y, a.y);
            *(float2*)&Asd[lc + 2][2 * row] = make_float2(a.z, a.z);
            *(float2*)&Asd[lc + 3][2 * row] = make_float2(a.w, a.w);
            float4 wv = *(const float4*)&W[(size_t)(n0 + row) * K + k0 + lc];
            Bs[lc + 0][row] = wv.x; Bs[lc + 1][row] = wv.y;
            Bs[lc + 2][row] = wv.z; Bs[lc + 3][row] = wv.w;
        }
        __syncthreads();
#pragma unroll
        for (int k = 0; k < 16; k++) {
            // 8 duplicated A values {a_m,a_m}, m = ty*8 + i  (4x LDS.128)
            ulonglong2 a01 = *(const ulonglong2*)&Asd[k][ty * 16 + 0];
            ulonglong2 a23 = *(const ulonglong2*)&Asd[k][ty * 16 + 4];
            ulonglong2 a45 = *(const ulonglong2*)&Asd[k][ty * 16 + 8];
            ulonglong2 a67 = *(const ulonglong2*)&Asd[k][ty * 16 + 12];
            // 4 B pairs {b_2j, b_2j+1}, n = n0 + tx*8 + .. (2x LDS.128)
            ulonglong2 b01 = *(const ulonglong2*)&Bs[k][tx * 8 + 0];
            ulonglong2 b23 = *(const ulonglong2*)&Bs[k][tx * 8 + 4];
            u64 av[8] = {a01.x, a01.y, a23.x, a23.y, a45.x, a45.y, a67.x, a67.y};
            u64 bv[4] = {b01.x, b01.y, b23.x, b23.y};
#pragma unroll
            for (int i = 0; i < 8; i++)
#pragma unroll
                for (int j = 0; j < 4; j++)
                    acc2[i][j] = ffma2(av[i], bv[j], acc2[i][j]);
        }
        __syncthreads();
    }

    // epilogue: bias add, store Y, fused column sum/sumsq
    float cs[8], cq[8];
#pragma unroll
    for (int j = 0; j < 8; j++) { cs[j] = 0.f; cq[j] = 0.f; }
#pragma unroll
    for (int i = 0; i < 8; i++) {
        int m = m0 + ty * 8 + i;
        float v[8];
#pragma unroll
        for (int j = 0; j < 4; j++) {
            float2 p = *(float2*)&acc2[i][j];
            v[2 * j]     = p.x + bias[n0 + tx * 8 + 2 * j];
            v[2 * j + 1] = p.y + bias[n0 + tx * 8 + 2 * j + 1];
        }
#pragma unroll
        for (int j = 0; j < 8; j++) {
            cs[j] += v[j];
            cq[j] = fmaf(v[j], v[j], cq[j]);
        }
        *(float4*)&Y[(size_t)m * ldc + n0 + tx * 8]     = make_float4(v[0], v[1], v[2], v[3]);
        *(float4*)&Y[(size_t)m * ldc + n0 + tx * 8 + 4] = make_float4(v[4], v[5], v[6], v[7]);
    }
    // block reduction over ty (reuse Asd smem; loop ended with __syncthreads)
#pragma unroll
    for (int j = 0; j < 8; j++) {
        Asd[ty][tx * 8 + j]       = cs[j];
        Asd[ty][tx * 8 + j + 132] = cq[j];
    }
    __syncthreads();
    if (tid < 128) {
        float s = 0.f, q = 0.f;
#pragma unroll
        for (int t = 0; t < 16; t++) {
            s += Asd[t][tid];
            q += Asd[t][tid + 132];
        }
        atomicAdd(&osum[n0 + tid], s);
        atomicAdd(&osq[n0 + tid], q);
    }
}

__global__ void finalize_kernel(const float* __restrict__ sum, const float* __restrict__ sq,
                                const float* __restrict__ g, const float* __restrict__ be,
                                float* __restrict__ sc, float* __restrict__ sh)
{
    int c = threadIdx.x;
    float mean = sum[c] * (1.f / MM);
    float var  = sq[c] * (1.f / MM) - mean * mean;
    float s = g[c] * rsqrtf(var + 1e-5f);
    sc[c] = s;
    sh[c] = fmaf(-mean, s, be[c]);
}

// ---------------- BN2 + ReLU + transpose to out[b][c][n] ----------------
__global__ void writeout_kernel(float* __restrict__ out)
{
    __shared__ float tile[32][33];
    int b  = blockIdx.z;
    int n0 = blockIdx.x * 32, c0 = blockIdx.y * 32;
    int tx = threadIdx.x, ty = threadIdx.y;
#pragma unroll
    for (int i = 0; i < 4; i++) {
        int n = n0 + ty + i * 8;
        float v = g_Y2[((size_t)b * NN + n) * H2 + c0 + tx];
        v = fmaxf(fmaf(v, g_sc2[c0 + tx], g_sh2[c0 + tx]), 0.f);
        tile[ty + i * 8][tx] = v;     // tile[n_local][c_local]
    }
    __syncthreads();
#pragma unroll
    for (int i = 0; i < 4; i++) {
        int c = c0 + ty + i * 8;
        out[((size_t)b * H2 + c) * NN + n0 + tx] = tile[tx][ty + i * 8];
    }
}

// ---------------- launch ----------------
extern "C" void kernel_launch(void* const* d_in, const int* in_sizes, int n_in,
                              void* d_out, int out_size)
{
    const float* xyz1    = (const float*)d_in[0];
    const float* xyz2    = (const float*)d_in[1];
    const float* points1 = (const float*)d_in[2];
    const float* points2 = (const float*)d_in[3];
    const float* W1  = (const float*)d_in[4];
    const float* b1  = (const float*)d_in[5];
    const float* g1  = (const float*)d_in[6];
    const float* be1 = (const float*)d_in[7];
    const float* W2  = (const float*)d_in[8];
    const float* b2  = (const float*)d_in[9];
    const float* g2  = (const float*)d_in[10];
    const float* be2 = (const float*)d_in[11];
    float* out = (float*)d_out;

    float *pX, *pY1, *pY2, *pP2T;
    float *psum1, *psq1, *psum2, *psq2, *psc1, *psh1, *psc2, *psh2;
    cudaGetSymbolAddress((void**)&pX,   g_X);
    cudaGetSymbolAddress((void**)&pY1,  g_Y1);
    cudaGetSymbolAddress((void**)&pY2,  g_Y2);
    cudaGetSymbolAddress((void**)&pP2T, g_P2T);
    cudaGetSymbolAddress((void**)&psum1, g_sum1);
    cudaGetSymbolAddress((void**)&psq1,  g_sq1);
    cudaGetSymbolAddress((void**)&psum2, g_sum2);
    cudaGetSymbolAddress((void**)&psq2,  g_sq2);
    cudaGetSymbolAddress((void**)&psc1,  g_sc1);
    cudaGetSymbolAddress((void**)&psh1,  g_sh1);
    cudaGetSymbolAddress((void**)&psc2,  g_sc2);
    cudaGetSymbolAddress((void**)&psh2,  g_sh2);

    zero_stats_kernel<<<1, 256>>>();

    // points1 [B,128,N] -> X[:, 0:128]   (ld 384)
    transpose_kernel<<<dim3(NN / 32, C1K / 32, BB), dim3(32, 8)>>>(points1, pX, C1K, NN, INCH);
    // points2 [B,256,S] -> P2T [B,S,256]
    transpose_kernel<<<dim3(SS / 32, C2K / 32, BB), dim3(32, 8)>>>(points2, pP2T, C2K, SS, C2K);

    knn_kernel<<<dim3(NN / 512, BB), 256>>>(xyz1, xyz2);
    interp_kernel<<<dim3(NN / 32, BB), 256>>>();

    // layer 1: [M,384] @ [384,256]   (stats fused)
    gemm_kernel<INCH, false><<<dim3(MM / 128, H1 / 128), 256>>>(pX, W1, b1, nullptr, nullptr, pY1, H1, psum1, psq1);
    finalize_kernel<<<1, H1>>>(psum1, psq1, g1, be1, psc1, psh1);

    // layer 2: BN1+ReLU fused into A-load, [M,256] @ [256,128]   (stats fused)
    gemm_kernel<H1, true><<<dim3(MM / 128, H2 / 128), 256>>>(pY1, W2, b2, psc1, psh1, pY2, H2, psum2, psq2);
    finalize_kernel<<<1, H2>>>(psum2, psq2, g2, be2, psc2, psh2);

    // BN2 + ReLU + transpose to [B,128,N]
    writeout_kernel<<<dim3(NN / 32, H2 / 32, BB), dim3(32, 8)>>>(out);
}

// round 5
// speedup vs baseline: 1.4412x; 1.4412x over previous
#include <cuda_runtime.h>
#include <cuda_bf16.h>
#include <cstdint>

// Problem constants
#define BB   8
#define NN   8192
#define SS   2048
#define C1K  128
#define C2K  256
#define INCH 384            // C1 + C2
#define H1   256
#define H2   128
#define MM   (BB * NN)      // 65536 total points

// ---------------- scratch (static device globals; no allocation) ----------------
__device__ __nv_bfloat16 g_Xh [MM * (size_t)INCH];   // split-hi of concat(p1, interp)
__device__ __nv_bfloat16 g_Xl [MM * (size_t)INCH];   // split-lo
__device__ __nv_bfloat16 g_W1h[H1 * INCH], g_W1l[H1 * INCH];
__device__ __nv_bfloat16 g_W2h[H2 * H1],   g_W2l[H2 * H1];
__device__ __nv_bfloat16 g_A2h[MM * (size_t)H1], g_A2l[MM * (size_t)H1]; // bn1+relu(Y1) split
__device__ float g_Y1 [MM * (size_t)H1];     // pre-BN layer1 out   [M, 256]
__device__ float g_Y2 [MM * (size_t)H2];     // pre-BN layer2 out   [M, 128]
__device__ float g_P2T[BB * (size_t)SS * C2K]; // points2 transposed [B, S, C2]
__device__ int   g_idx[MM * 3];
__device__ float g_wt [MM * 3];
__device__ float g_sum1[H1], g_sq1[H1], g_sum2[H2], g_sq2[H2];
__device__ float g_sc1 [H1], g_sh1[H1], g_sc2 [H2], g_sh2[H2];

// ---------------- mma.sync / ldmatrix helpers (baseline PTX, no 'a' features) ----
#define LDSM_X4(r0, r1, r2, r3, addr) \
    asm volatile("ldmatrix.sync.aligned.m8n8.x4.shared.b16 {%0,%1,%2,%3}, [%4];" \
        : "=r"(r0), "=r"(r1), "=r"(r2), "=r"(r3) : "r"(addr))

#define MMA_BF16(d, a0, a1, a2, a3, b0, b1) \
    asm volatile("mma.sync.aligned.m16n8k16.row.col.f32.bf16.bf16.f32 " \
        "{%0,%1,%2,%3}, {%4,%5,%6,%7}, {%8,%9}, {%0,%1,%2,%3};" \
        : "+f"((d)[0]), "+f"((d)[1]), "+f"((d)[2]), "+f"((d)[3]) \
        : "r"(a0), "r"(a1), "r"(a2), "r"(a3), "r"(b0), "r"(b1))

__device__ __forceinline__ uint32_t smem_to_u32(const void* p) {
    uint32_t a;
    asm("{ .reg .u64 t; cvta.to.shared.u64 t, %1; cvt.u32.u64 %0, t; }" : "=r"(a) : "l"(p));
    return a;
}

__device__ __forceinline__ void split_bf16(float x, __nv_bfloat16& h, __nv_bfloat16& l) {
    h = __float2bfloat16(x);
    l = __float2bfloat16(x - __bfloat162float(h));
}

// ---------------- zero the per-channel accumulators ----------------
__global__ void zero_stats_kernel() {
    int t = threadIdx.x;
    g_sum1[t] = 0.f; g_sq1[t] = 0.f;
    if (t < H2) { g_sum2[t] = 0.f; g_sq2[t] = 0.f; }
}

// ---------------- elementwise fp32 -> bf16 hi/lo split ----------------
__global__ void split_kernel(const float* __restrict__ src,
                             __nv_bfloat16* __restrict__ h, __nv_bfloat16* __restrict__ l, int n)
{
    int i = blockIdx.x * 256 + threadIdx.x;
    if (i < n) split_bf16(src[i], h[i], l[i]);
}

// ---------------- tiled transpose: src [B][C][L] fp32 -> dst [B][L][ldDst] fp32 ----------------
__global__ void transpose_kernel(const float* __restrict__ src, float* __restrict__ dst,
                                 int C, int L, int ldDst)
{
    __shared__ float tile[32][33];
    int b  = blockIdx.z;
    int l0 = blockIdx.x * 32, c0 = blockIdx.y * 32;
    const float* s = src + (size_t)b * C * L;
    float*       d = dst + (size_t)b * L * ldDst;
    int tx = threadIdx.x, ty = threadIdx.y;
#pragma unroll
    for (int i = 0; i < 4; i++)
        tile[ty + i * 8][tx] = s[(size_t)(c0 + ty + i * 8) * L + l0 + tx];
    __syncthreads();
#pragma unroll
    for (int i = 0; i < 4; i++)
        d[(size_t)(l0 + ty + i * 8) * ldDst + c0 + tx] = tile[tx][ty + i * 8];
}

// ---------------- points1 [B,128,N] -> Xh/Xl [B*N, 384] cols 0:128 (bf16 split) ----------------
__global__ void transpose_split_kernel(const float* __restrict__ src)
{
    __shared__ float tile[32][33];
    int b  = blockIdx.z;
    int l0 = blockIdx.x * 32, c0 = blockIdx.y * 32;
    const float* s = src + (size_t)b * C1K * NN;
    int tx = threadIdx.x, ty = threadIdx.y;
#pragma unroll
    for (int i = 0; i < 4; i++)
        tile[ty + i * 8][tx] = s[(size_t)(c0 + ty + i * 8) * NN + l0 + tx];
    __syncthreads();
#pragma unroll
    for (int i = 0; i < 4; i++) {
        int l = l0 + ty + i * 8;
        size_t o = ((size_t)b * NN + l) * INCH + c0 + tx;
        __nv_bfloat16 h, lo;
        split_bf16(tile[tx][ty + i * 8], h, lo);
        g_Xh[o] = h; g_Xl[o] = lo;
    }
}

// ---------------- 3-NN over S=2048 candidates (smem resident) ----------------
__global__ void knn_kernel(const float* __restrict__ xyz1, const float* __restrict__ xyz2)
{
    __shared__ float4 sq[SS];               // {x, y, z, |q|^2}  32KB
    int b = blockIdx.y;
    const float* x2 = xyz2 + (size_t)b * 3 * SS;
    for (int s = threadIdx.x; s < SS; s += blockDim.x) {
        float qx = x2[s], qy = x2[SS + s], qz = x2[2 * SS + s];
        sq[s] = make_float4(qx, qy, qz, qx * qx + qy * qy + qz * qz);
    }
    __syncthreads();

    int n = blockIdx.x * blockDim.x + threadIdx.x;
    const float* x1 = xyz1 + (size_t)b * 3 * NN;
    float px = x1[n], py = x1[NN + n], pz = x1[2 * NN + n];
    float mx = -2.f * px, my = -2.f * py, mz = -2.f * pz;
    float p2 = px * px + py * py + pz * pz;

    float d0 = 1e30f, d1 = 1e30f, d2 = 1e30f;
    int   i0 = 0, i1 = 0, i2 = 0;
#pragma unroll 4
    for (int s = 0; s < SS; s++) {
        float4 q = sq[s];
        float t = fmaf(mx, q.x, fmaf(my, q.y, fmaf(mz, q.z, q.w)));
        if (t < d2) {
            if (t < d1) {
                d2 = d1; i2 = i1;
                if (t < d0) { d1 = d0; i1 = i0; d0 = t; i0 = s; }
                else        { d1 = t;  i1 = s; }
            } else { d2 = t; i2 = s; }
        }
    }
    float e0 = d0 + p2, e1 = d1 + p2, e2 = d2 + p2;
    float r0 = 1.f / (e0 + 1e-8f), r1 = 1.f / (e1 + 1e-8f), r2 = 1.f / (e2 + 1e-8f);
    float rs = 1.f / (r0 + r1 + r2);
    size_t base = ((size_t)b * NN + n) * 3;
    g_idx[base] = i0; g_idx[base + 1] = i1; g_idx[base + 2] = i2;
    g_wt [base] = r0 * rs; g_wt[base + 1] = r1 * rs; g_wt[base + 2] = r2 * rs;
}

// ---------------- weighted gather of 3 rows from P2T -> Xh/Xl[:,128:384] ----------------
__global__ void interp_kernel()
{
    int b  = blockIdx.y;
    int c  = threadIdx.x;                  // channel 0..255
    int n0 = blockIdx.x * 32;
    const float* p2t = g_P2T + (size_t)b * SS * C2K;
#pragma unroll 4
    for (int r = 0; r < 32; r++) {
        size_t m = (size_t)b * NN + n0 + r;
        int   j0 = g_idx[m * 3], j1 = g_idx[m * 3 + 1], j2 = g_idx[m * 3 + 2];
        float w0 = g_wt[m * 3], w1 = g_wt[m * 3 + 1], w2 = g_wt[m * 3 + 2];
        float v = w0 * p2t[(size_t)j0 * C2K + c]
                + w1 * p2t[(size_t)j1 * C2K + c]
                + w2 * p2t[(size_t)j2 * C2K + c];
        __nv_bfloat16 h, l;
        split_bf16(v, h, l);
        g_Xh[m * INCH + C1K + c] = h;
        g_Xl[m * INCH + C1K + c] = l;
    }
}

// ---------------- BN1 + ReLU + bf16 split of Y1 -> A2h/A2l ----------------
__global__ void bnrelu_split_kernel()
{
    size_t i = (size_t)blockIdx.x * 256 + threadIdx.x;
    int c = threadIdx.x;                  // 256 threads == H1 channels, aligned
    float v = fmaxf(fmaf(g_Y1[i], g_sc1[c], g_sh1[c]), 0.f);
    __nv_bfloat16 h, l;
    split_bf16(v, h, l);
    g_A2h[i] = h; g_A2l[i] = l;
}

// ================= mma.sync bf16 split GEMM =================
// Y[M tile=128][N tile=128] += (Ah+Al)[m][k] * (Bh+Bl)[n][k] (3-product split) + bias
// BK=32, double-buffered dynamic smem, 80B-padded rows (conflict-free ldmatrix).
// 8 warps: 2 (m) x 4 (n); warp tile 64x32; frags m16n8k16.
template <int K>
__global__ __launch_bounds__(256, 1) void tc_gemm_kernel(
    const __nv_bfloat16* __restrict__ Ah, const __nv_bfloat16* __restrict__ Al,
    const __nv_bfloat16* __restrict__ Bh, const __nv_bfloat16* __restrict__ Bl,
    const float* __restrict__ bias, float* __restrict__ Y, int ldc)
{
    constexpr int NCH   = K / 32;          // K chunks
    constexpr int KR4   = K / 8;           // int4 per global row
    constexpr int MAT   = 128 * 80;        // bytes per smem matrix (padded)
    constexpr int STAGE = 4 * MAT;         // Ah, Al, Bh, Bl

    extern __shared__ char smem[];
    uint32_t sb32 = smem_to_u32(smem);

    int tid = threadIdx.x;
    int lane = tid & 31, wid = tid >> 5;
    int warpM = wid >> 2, warpN = wid & 3;
    int m0 = blockIdx.x * 128;
    int n0 = blockIdx.y * 128;

    const int4* gA[2] = { (const int4*)Ah + (size_t)m0 * KR4,
                          (const int4*)Al + (size_t)m0 * KR4 };
    const int4* gB[2] = { (const int4*)Bh + (size_t)n0 * KR4,
                          (const int4*)Bl + (size_t)n0 * KR4 };

    // per-thread loader coords: 512 int4 per matrix, 2 per thread
    int ldr = 0, ldc4 = 0;
    {
        ldr = tid >> 2; ldc4 = tid & 3;    // handled rows tid>>2 and tid>>2 + 64
    }

    auto load_stage = [&](int c, int stage) {
        char* s = smem + stage * STAGE;
#pragma unroll
        for (int h = 0; h < 2; h++) {
#pragma unroll
            for (int it = 0; it < 2; it++) {
                int r = ldr + it * 64;
                *(int4*)(s + h * MAT + r * 80 + ldc4 * 16) = gA[h][(size_t)r * KR4 + c * 4 + ldc4];
            }
#pragma unroll
            for (int it = 0; it < 2; it++) {
                int r = ldr + it * 64;
                *(int4*)(s + (2 + h) * MAT + r * 80 + ldc4 * 16) = gB[h][(size_t)r * KR4 + c * 4 + ldc4];
            }
        }
    };

    float acc[4][4][4];
#pragma unroll
    for (int i = 0; i < 4; i++)
#pragma unroll
        for (int j = 0; j < 4; j++)
#pragma unroll
            for (int r = 0; r < 4; r++) acc[i][j][r] = 0.f;

    // ldmatrix per-lane address pieces
    int aRow  = warpM * 64 + (lane & 15);
    int aColB = (lane >> 4) * 16;                       // bytes
    int bRow  = warpN * 32 + (lane & 7) + ((lane >> 4) << 3);
    int bColB = ((lane >> 3) & 1) * 16;                 // bytes

    load_stage(0, 0);
    __syncthreads();

#pragma unroll 1
    for (int c = 0; c < NCH; c++) {
        if (c + 1 < NCH) load_stage(c + 1, (c + 1) & 1);

        uint32_t sA = sb32 + (c & 1) * STAGE;
        uint32_t sB = sA + 2 * MAT;
#pragma unroll
        for (int ks = 0; ks < 2; ks++) {
            uint32_t ah[4][4], al[4][4], bh[4][2], bl[4][2];
#pragma unroll
            for (int mi = 0; mi < 4; mi++) {
                uint32_t addr = sA + (aRow + mi * 16) * 80 + aColB + ks * 32;
                LDSM_X4(ah[mi][0], ah[mi][1], ah[mi][2], ah[mi][3], addr);
                LDSM_X4(al[mi][0], al[mi][1], al[mi][2], al[mi][3], addr + MAT);
            }
#pragma unroll
            for (int nj2 = 0; nj2 < 2; nj2++) {
                uint32_t addr = sB + (bRow + nj2 * 16) * 80 + bColB + ks * 32;
                LDSM_X4(bh[nj2 * 2][0], bh[nj2 * 2][1], bh[nj2 * 2 + 1][0], bh[nj2 * 2 + 1][1], addr);
                LDSM_X4(bl[nj2 * 2][0], bl[nj2 * 2][1], bl[nj2 * 2 + 1][0], bl[nj2 * 2 + 1][1], addr + MAT);
            }
#pragma unroll
            for (int mi = 0; mi < 4; mi++)
#pragma unroll
                for (int nj = 0; nj < 4; nj++) {
                    MMA_BF16(acc[mi][nj], ah[mi][0], ah[mi][1], ah[mi][2], ah[mi][3],
                             bh[nj][0], bh[nj][1]);
                    MMA_BF16(acc[mi][nj], ah[mi][0], ah[mi][1], ah[mi][2], ah[mi][3],
                             bl[nj][0], bl[nj][1]);
                    MMA_BF16(acc[mi][nj], al[mi][0], al[mi][1], al[mi][2], al[mi][3],
                             bh[nj][0], bh[nj][1]);
                }
        }
        __syncthreads();
    }

    // epilogue: D[m][n] + bias -> Y (fp32)
    int g = lane >> 2, tig = lane & 3;
#pragma unroll
    for (int mi = 0; mi < 4; mi++) {
        int r0 = m0 + warpM * 64 + mi * 16 + g;
#pragma unroll
        for (int nj = 0; nj < 4; nj++) {
            int cc = n0 + warpN * 32 + nj * 8 + 2 * tig;
            float bx = bias[cc], by = bias[cc + 1];
            *(float2*)&Y[(size_t)r0 * ldc + cc] =
                make_float2(acc[mi][nj][0] + bx, acc[mi][nj][1] + by);
            *(float2*)&Y[(size_t)(r0 + 8) * ldc + cc] =
                make_float2(acc[mi][nj][2] + bx, acc[mi][nj][3] + by);
        }
    }
}

// ---------------- per-channel sum / sumsq over all M rows ----------------
__global__ void colstats_kernel(const float* __restrict__ Y, int C,
                                float* __restrict__ sum, float* __restrict__ sq)
{
    int c = threadIdx.x;
    float s = 0.f, q = 0.f;
    for (int m = blockIdx.x; m < MM; m += gridDim.x) {
        float v = Y[(size_t)m * C + c];
        s += v; q = fmaf(v, v, q);
    }
    atomicAdd(&sum[c], s);
    atomicAdd(&sq[c], q);
}

__global__ void finalize_kernel(const float* __restrict__ sum, const float* __restrict__ sq,
                                const float* __restrict__ g, const float* __restrict__ be,
                                float* __restrict__ sc, float* __restrict__ sh)
{
    int c = threadIdx.x;
    float mean = sum[c] * (1.f / MM);
    float var  = sq[c] * (1.f / MM) - mean * mean;
    float s = g[c] * rsqrtf(var + 1e-5f);
    sc[c] = s;
    sh[c] = fmaf(-mean, s, be[c]);
}

// ---------------- BN2 + ReLU + transpose to out[b][c][n] ----------------
__global__ void writeout_kernel(float* __restrict__ out)
{
    __shared__ float tile[32][33];
    int b  = blockIdx.z;
    int n0 = blockIdx.x * 32, c0 = blockIdx.y * 32;
    int tx = threadIdx.x, ty = threadIdx.y;
#pragma unroll
    for (int i = 0; i < 4; i++) {
        int n = n0 + ty + i * 8;
        float v = g_Y2[((size_t)b * NN + n) * H2 + c0 + tx];
        v = fmaxf(fmaf(v, g_sc2[c0 + tx], g_sh2[c0 + tx]), 0.f);
        tile[ty + i * 8][tx] = v;     // tile[n_local][c_local]
    }
    __syncthreads();
#pragma unroll
    for (int i = 0; i < 4; i++) {
        int c = c0 + ty + i * 8;
        out[((size_t)b * H2 + c) * NN + n0 + tx] = tile[tx][ty + i * 8];
    }
}

// ---------------- launch ----------------
extern "C" void kernel_launch(void* const* d_in, const int* in_sizes, int n_in,
                              void* d_out, int out_size)
{
    const float* xyz1    = (const float*)d_in[0];
    const float* xyz2    = (const float*)d_in[1];
    const float* points1 = (const float*)d_in[2];
    const float* points2 = (const float*)d_in[3];
    const float* W1  = (const float*)d_in[4];
    const float* b1  = (const float*)d_in[5];
    const float* g1  = (const float*)d_in[6];
    const float* be1 = (const float*)d_in[7];
    const float* W2  = (const float*)d_in[8];
    const float* b2  = (const float*)d_in[9];
    const float* g2  = (const float*)d_in[10];
    const float* be2 = (const float*)d_in[11];
    float* out = (float*)d_out;

    float *pY1, *pY2, *pP2T;
    float *psum1, *psq1, *psum2, *psq2, *psc1, *psh1, *psc2, *psh2;
    __nv_bfloat16 *pXh, *pXl, *pW1h, *pW1l, *pW2h, *pW2l, *pA2h, *pA2l;
    cudaGetSymbolAddress((void**)&pY1,  g_Y1);
    cudaGetSymbolAddress((void**)&pY2,  g_Y2);
    cudaGetSymbolAddress((void**)&pP2T, g_P2T);
    cudaGetSymbolAddress((void**)&pXh,  g_Xh);
    cudaGetSymbolAddress((void**)&pXl,  g_Xl);
    cudaGetSymbolAddress((void**)&pW1h, g_W1h);
    cudaGetSymbolAddress((void**)&pW1l, g_W1l);
    cudaGetSymbolAddress((void**)&pW2h, g_W2h);
    cudaGetSymbolAddress((void**)&pW2l, g_W2l);
    cudaGetSymbolAddress((void**)&pA2h, g_A2h);
    cudaGetSymbolAddress((void**)&pA2l, g_A2l);
    cudaGetSymbolAddress((void**)&psum1, g_sum1);
    cudaGetSymbolAddress((void**)&psq1,  g_sq1);
    cudaGetSymbolAddress((void**)&psum2, g_sum2);
    cudaGetSymbolAddress((void**)&psq2,  g_sq2);
    cudaGetSymbolAddress((void**)&psc1,  g_sc1);
    cudaGetSymbolAddress((void**)&psh1,  g_sh1);
    cudaGetSymbolAddress((void**)&psc2,  g_sc2);
    cudaGetSymbolAddress((void**)&psh2,  g_sh2);

    // dynamic smem: 2 stages x 4 matrices x 128 rows x 80B = 81920
    const int smem_bytes = 2 * 4 * 128 * 80;
    cudaFuncSetAttribute(tc_gemm_kernel<INCH>,
                         cudaFuncAttributeMaxDynamicSharedMemorySize, smem_bytes);
    cudaFuncSetAttribute(tc_gemm_kernel<H1>,
                         cudaFuncAttributeMaxDynamicSharedMemorySize, smem_bytes);

    zero_stats_kernel<<<1, 256>>>();

    // weight splits
    split_kernel<<<(H1 * INCH + 255) / 256, 256>>>(W1, pW1h, pW1l, H1 * INCH);
    split_kernel<<<(H2 * H1 + 255) / 256, 256>>>(W2, pW2h, pW2l, H2 * H1);

    // points1 [B,128,N] -> Xh/Xl cols 0:128
    transpose_split_kernel<<<dim3(NN / 32, C1K / 32, BB), dim3(32, 8)>>>(points1);
    // points2 [B,256,S] -> P2T [B,S,256] fp32
    transpose_kernel<<<dim3(SS / 32, C2K / 32, BB), dim3(32, 8)>>>(points2, pP2T, C2K, SS, C2K);

    knn_kernel<<<dim3(NN / 128, BB), 128>>>(xyz1, xyz2);
    interp_kernel<<<dim3(NN / 32, BB), 256>>>();

    // layer 1: [M,384] @ [384,256] via mma.sync (bf16 split), grid (512, 2)
    tc_gemm_kernel<INCH><<<dim3(MM / 128, H1 / 128), 256, smem_bytes>>>(
        pXh, pXl, pW1h, pW1l, b1, pY1, H1);
    colstats_kernel<<<512, H1>>>(pY1, H1, psum1, psq1);
    finalize_kernel<<<1, H1>>>(psum1, psq1, g1, be1, psc1, psh1);

    // BN1 + ReLU + split
    bnrelu_split_kernel<<<MM * H1 / 256, 256>>>();

    // layer 2: [M,256] @ [256,128], grid (512, 1)
    tc_gemm_kernel<H1><<<dim3(MM / 128, H2 / 128), 256, smem_bytes>>>(
        pA2h, pA2l, pW2h, pW2l, b2, pY2, H2);
    colstats_kernel<<<512, H2>>>(pY2, H2, psum2, psq2);
    finalize_kernel<<<1, H2>>>(psum2, psq2, g2, be2, psc2, psh2);

    // BN2 + ReLU + transpose to [B,128,N]
    writeout_kernel<<<dim3(NN / 32, H2 / 32, BB), dim3(32, 8)>>>(out);
}